// round 4
// baseline (speedup 1.0000x reference)
#include <cuda_runtime.h>
#include <cuda_bf16.h>
#include <math.h>

// Problem constants
#define B 64
#define NA 33600            // 160*160 + 80*80 + 40*40
#define TOPK 500
#define TOPK_PAD 512
#define SCORE_THRESH 0.3f
#define NMS_THRESH 0.5f
#define CLASS_OFFSET 10000.0f

// ---------------- scratch (static device allocations; no runtime alloc) ----
__device__ float4 g_boxes [B * NA];          // decoded boxes
__device__ float  g_scores[B * NA];          // masked scores (score or -1)
__device__ unsigned char g_labels[B * NA];   // argmax label (0/1)
__device__ int    g_topidx[B * TOPK_PAD];    // sorted top-k anchor indices

// ------------------------------------------------------------ exp/sigmoid --
// Correctly-rounded float exp: CUDA double exp is accurate to <1 double-ulp,
// so rounding to float reproduces glibc expf (used by XLA:CPU via llvm.exp.f32)
// for all practical inputs.
__device__ __forceinline__ float exp_cr(float x) {
    return (float)exp((double)x);
}

// XLA logistic: 1 / (1 + exp(-x)), separate IEEE fp32 roundings, no FMA.
__device__ __forceinline__ float sigmoidf_(float x) {
    float nx = -x;                       // exact
    float e  = exp_cr(nx);
    return __fdiv_rn(1.0f, __fadd_rn(1.0f, e));
}

// ---------------------------------------------------------------- decode ---
__global__ void decode_kernel(const float* __restrict__ cls,
                              const float* __restrict__ reg,
                              const float* __restrict__ obj,
                              int H, int W, float stride, int base)
{
    int HW = H * W;
    int t = blockIdx.x * blockDim.x + threadIdx.x;
    int total = B * HW;
    if (t >= total) return;
    int b = t / HW;
    int p = t - b * HW;
    int y = p / W;
    int x = p - y * W;

    float o  = obj[b * HW + p];
    float c0 = cls[(b * 2 + 0) * HW + p];
    float c1 = cls[(b * 2 + 1) * HW + p];
    float so = sigmoidf_(o);
    float s0 = __fmul_rn(so, sigmoidf_(c0));
    float s1 = __fmul_rn(so, sigmoidf_(c1));
    int   label = (s1 > s0) ? 1 : 0;
    float smax  = fmaxf(s0, s1);
    float masked = (smax > SCORE_THRESH) ? smax : -1.0f;

    float dx = reg[(b * 4 + 0) * HW + p];
    float dy = reg[(b * 4 + 1) * HW + p];
    float dw = reg[(b * 4 + 2) * HW + p];
    float dh = reg[(b * 4 + 3) * HW + p];
    float cx = __fmul_rn(__fadd_rn((float)x, sigmoidf_(dx)), stride);
    float cy = __fmul_rn(__fadd_rn((float)y, sigmoidf_(dy)), stride);
    float w  = __fmul_rn(exp_cr(dw), stride);
    float h  = __fmul_rn(exp_cr(dh), stride);

    float wh = __fdiv_rn(w, 2.0f);
    float hh = __fdiv_rn(h, 2.0f);
    float4 box;
    box.x = __fsub_rn(cx, wh);
    box.y = __fsub_rn(cy, hh);
    box.z = __fadd_rn(cx, wh);
    box.w = __fadd_rn(cy, hh);

    int gi = b * NA + base + p;
    g_boxes[gi]  = box;
    g_scores[gi] = masked;
    g_labels[gi] = (unsigned char)label;
}

// --------------------------------------------------------------- top-k -----
// key = ordered(score) << 32 | ~idx  -> 64-bit descending order ==
// (score desc, idx asc) == jax.lax.top_k stable ordering. Keys are unique.
__device__ __forceinline__ unsigned int ordered_float(float f) {
    unsigned int u = __float_as_uint(f);
    return (u & 0x80000000u) ? ~u : (u | 0x80000000u);
}

__device__ __forceinline__ unsigned long long make_key(int b, int i) {
    unsigned int hi = ordered_float(g_scores[b * NA + i]);
    unsigned int lo = ~(unsigned int)i;
    return ((unsigned long long)hi << 32) | lo;
}

__global__ void topk_kernel()
{
    __shared__ unsigned int hist[256];
    __shared__ unsigned long long s_prefix;
    __shared__ int s_k;
    __shared__ int s_cnt;
    __shared__ unsigned int skey[TOPK_PAD];
    __shared__ int          sidx[TOPK_PAD];

    int b = blockIdx.x;
    int tid = threadIdx.x;
    int nthr = blockDim.x;

    if (tid == 0) { s_prefix = 0ull; s_k = TOPK; s_cnt = 0; }
    __syncthreads();

    // 8-pass (8-bit digit) radix select for the exact 500th-largest key
    for (int p = 7; p >= 0; --p) {
        for (int d = tid; d < 256; d += nthr) hist[d] = 0;
        __syncthreads();
        unsigned long long pref = s_prefix;
        int sh = (p + 1) * 8;
        for (int i = tid; i < NA; i += nthr) {
            unsigned long long key = make_key(b, i);
            bool match = (p == 7) || ((key >> sh) == (pref >> sh));
            if (match)
                atomicAdd(&hist[(unsigned int)(key >> (p * 8)) & 0xFFu], 1u);
        }
        __syncthreads();
        if (tid == 0) {
            int k = s_k;
            for (int d = 255; d >= 0; --d) {
                int c = (int)hist[d];
                if (k <= c) {
                    s_prefix = pref | ((unsigned long long)d << (p * 8));
                    break;
                }
                k -= c;
            }
            s_k = k;
        }
        __syncthreads();
    }

    unsigned long long pivot = s_prefix;  // exact 500th largest (unique keys)

    // gather the exactly-500 keys >= pivot
    for (int i = tid; i < NA; i += nthr) {
        unsigned long long key = make_key(b, i);
        if (key >= pivot) {
            int pos = atomicAdd(&s_cnt, 1);
            if (pos < TOPK_PAD) { skey[pos] = (unsigned int)(key >> 32); sidx[pos] = i; }
        }
    }
    __syncthreads();
    int cnt = s_cnt;
    for (int s = tid; s < TOPK_PAD; s += nthr) {
        if (s >= cnt) { skey[s] = 0u; sidx[s] = 0x7FFFFFFF; }  // key64 below all real keys
    }
    __syncthreads();

    // bitonic sort (descending), 512 elems, 512 threads
    for (int k = 2; k <= TOPK_PAD; k <<= 1) {
        for (int j = k >> 1; j > 0; j >>= 1) {
            int i = tid;
            int ixj = i ^ j;
            if (ixj > i && i < TOPK_PAD) {
                unsigned long long ka =
                    ((unsigned long long)skey[i] << 32) | (unsigned int)(~sidx[i]);
                unsigned long long kb =
                    ((unsigned long long)skey[ixj] << 32) | (unsigned int)(~sidx[ixj]);
                bool descending = ((i & k) == 0);
                bool do_swap = descending ? (ka < kb) : (ka > kb);
                if (do_swap) {
                    unsigned int tk = skey[i]; skey[i] = skey[ixj]; skey[ixj] = tk;
                    int ti = sidx[i]; sidx[i] = sidx[ixj]; sidx[ixj] = ti;
                }
            }
            __syncthreads();
        }
    }

    if (tid < TOPK) g_topidx[b * TOPK_PAD + tid] = sidx[tid];
}

// ----------------------------------------------------------------- NMS -----
__global__ void nms_kernel(float* __restrict__ out)
{
    __shared__ float sx1[TOPK_PAD], sy1[TOPK_PAD], sx2[TOPK_PAD], sy2[TOPK_PAD];
    __shared__ float sar[TOPK_PAD];
    __shared__ unsigned char svalid[TOPK_PAD];
    __shared__ unsigned char skeep[TOPK_PAD];
    __shared__ unsigned int adj[TOPK][16];   // IoU>=0.5 adjacency bitmatrix

    int b = blockIdx.x;
    int r = threadIdx.x;

    float4 bb = make_float4(0.f, 0.f, 0.f, 0.f);
    float  sc = -1.0f;
    int    lab = 0;

    if (r < TOPK) {
        int idx = g_topidx[b * TOPK_PAD + r];
        bb  = g_boxes[b * NA + idx];
        sc  = g_scores[b * NA + idx];
        lab = (int)g_labels[b * NA + idx];
        float off = __fmul_rn((float)lab, CLASS_OFFSET);
        float x1 = __fadd_rn(bb.x, off);
        float y1 = __fadd_rn(bb.y, off);
        float x2 = __fadd_rn(bb.z, off);
        float y2 = __fadd_rn(bb.w, off);
        sx1[r] = x1; sy1[r] = y1; sx2[r] = x2; sy2[r] = y2;
        // area on OFFSET boxes, separate roundings (match ref fp32 exactly)
        sar[r] = __fmul_rn(__fsub_rn(x2, x1), __fsub_rn(y2, y1));
        svalid[r] = (sc > SCORE_THRESH) ? 1 : 0;
    } else {
        sx1[r] = 0.f; sy1[r] = 0.f; sx2[r] = 0.f; sy2[r] = 0.f;
        sar[r] = 0.f; svalid[r] = 0;
    }
    __syncthreads();

    // each thread builds one adjacency row (500 IoUs), all ops separately rounded
    if (r < TOPK) {
        float x1 = sx1[r], y1 = sy1[r], x2 = sx2[r], y2 = sy2[r], ar = sar[r];
        #pragma unroll 1
        for (int w = 0; w < 16; ++w) {
            unsigned int bits = 0;
            #pragma unroll 1
            for (int jj = 0; jj < 32; ++jj) {
                int j = (w << 5) + jj;
                if (j < TOPK) {
                    float ix1 = fmaxf(x1, sx1[j]);
                    float iy1 = fmaxf(y1, sy1[j]);
                    float ix2 = fminf(x2, sx2[j]);
                    float iy2 = fminf(y2, sy2[j]);
                    float iw = fmaxf(__fsub_rn(ix2, ix1), 0.f);
                    float ih = fmaxf(__fsub_rn(iy2, iy1), 0.f);
                    float inter = __fmul_rn(iw, ih);
                    float uni = __fsub_rn(__fadd_rn(ar, sar[j]), inter);
                    float iou = __fdiv_rn(inter, __fadd_rn(uni, 1e-7f));
                    if (iou >= NMS_THRESH) bits |= (1u << jj);
                }
            }
            adj[r][w] = bits;
        }
    }
    __syncthreads();

    // serial greedy pass on warp 0: 16 lanes hold the suppression bitmask
    if (threadIdx.x < 32) {
        unsigned int supp = 0;
        int lane = threadIdx.x;
        for (int i = 0; i < TOPK; ++i) {
            unsigned int sw = __shfl_sync(0xFFFFFFFFu, supp, i >> 5);
            bool keep_i = svalid[i] && !((sw >> (i & 31)) & 1u);
            if (lane == 0) skeep[i] = keep_i ? 1 : 0;
            if (keep_i && lane < 16) supp |= adj[i][lane];
        }
    }
    __syncthreads();

    // outputs: [boxes (B*500*4)] [scores (B*500)] [labels (B*500)] [keep (B*500)]
    if (r < TOPK) {
        bool kp = skeep[r] != 0;
        int row = b * TOPK + r;
        float* ob = out + row * 4;
        ob[0] = kp ? bb.x : 0.f;
        ob[1] = kp ? bb.y : 0.f;
        ob[2] = kp ? bb.z : 0.f;
        ob[3] = kp ? bb.w : 0.f;
        const int SBASE = B * TOPK * 4;
        const int LBASE = SBASE + B * TOPK;
        const int KBASE = LBASE + B * TOPK;
        out[SBASE + row] = kp ? sc : 0.f;
        out[LBASE + row] = (float)lab;
        out[KBASE + row] = kp ? 1.f : 0.f;
    }
}

// --------------------------------------------------------------- launch ----
extern "C" void kernel_launch(void* const* d_in, const int* in_sizes, int n_in,
                              void* d_out, int out_size)
{
    const float* cls_p3 = (const float*)d_in[0];
    const float* reg_p3 = (const float*)d_in[1];
    const float* obj_p3 = (const float*)d_in[2];
    const float* cls_p4 = (const float*)d_in[3];
    const float* reg_p4 = (const float*)d_in[4];
    const float* obj_p4 = (const float*)d_in[5];
    const float* cls_p5 = (const float*)d_in[6];
    const float* reg_p5 = (const float*)d_in[7];
    const float* obj_p5 = (const float*)d_in[8];
    float* out = (float*)d_out;

    const int T = 256;
    // P3: 160x160, stride 8, base 0
    decode_kernel<<<(B * 160 * 160 + T - 1) / T, T>>>(cls_p3, reg_p3, obj_p3, 160, 160, 8.f, 0);
    // P4: 80x80, stride 16, base 25600
    decode_kernel<<<(B * 80 * 80 + T - 1) / T, T>>>(cls_p4, reg_p4, obj_p4, 80, 80, 16.f, 25600);
    // P5: 40x40, stride 32, base 32000
    decode_kernel<<<(B * 40 * 40 + T - 1) / T, T>>>(cls_p5, reg_p5, obj_p5, 40, 40, 32.f, 32000);

    topk_kernel<<<B, TOPK_PAD>>>();
    nms_kernel<<<B, TOPK_PAD>>>(out);
}

// round 5
// speedup vs baseline: 1.3718x; 1.3718x over previous
#include <cuda_runtime.h>
#include <cuda_bf16.h>
#include <math.h>

// Problem constants
#define B 64
#define NA 33600            // 160*160 + 80*80 + 40*40
#define TOPK 500
#define CAND 1024           // candidate buffer / sort size
#define NBIN 1024           // linear histogram bins over (0.3, 1.0]
#define SCORE_THRESH 0.3f
#define NMS_THRESH 0.5f
#define CLASS_OFFSET 10000.0f

// level boundaries
#define P3_END 25600
#define P4_END 32000

// ---------------- scratch (static device allocations; no runtime alloc) ----
__device__ float         g_scores[B * NA];   // masked scores (score or -1)
__device__ unsigned char g_labels[B * NA];   // argmax label (0/1)
__device__ int           g_topidx[B * TOPK]; // sorted top-k anchor indices

// ------------------------------------------------------------ exp/sigmoid --
// Correctly-rounded float exp via double exp (matches XLA:CPU expf). DO NOT
// change: R4 verified bit-compatibility (rel_err 1.6e-8, no decision flips).
__device__ __forceinline__ float exp_cr(float x) {
    return (float)exp((double)x);
}
// exact sigmoid, separate fp32 roundings (same sequence as R4)
__device__ __forceinline__ float sig_e(float x) {
    float e = exp_cr(-x);
    return __fdiv_rn(1.0f, __fadd_rn(1.0f, e));
}
// fast sigmoid for the prefilter only (abs error < ~2e-6)
__device__ __forceinline__ float sig_fast(float x) {
    return __fdividef(1.0f, 1.0f + __expf(-x));
}

// ------------------------------------------------------- decode (scores) ---
__global__ void decode_score_kernel(const float* __restrict__ cls3,
                                    const float* __restrict__ obj3,
                                    const float* __restrict__ cls4,
                                    const float* __restrict__ obj4,
                                    const float* __restrict__ cls5,
                                    const float* __restrict__ obj5)
{
    int t = blockIdx.x * blockDim.x + threadIdx.x;
    if (t >= B * NA) return;
    int b = t / NA;
    int a = t - b * NA;

    const float* cls; const float* obj; int HW, p;
    if (a < P3_END)      { cls = cls3; obj = obj3; HW = 25600; p = a; }
    else if (a < P4_END) { cls = cls4; obj = obj4; HW = 6400;  p = a - P3_END; }
    else                 { cls = cls5; obj = obj5; HW = 1600;  p = a - P4_END; }

    float o  = obj[b * HW + p];
    float c0 = cls[(b * 2 + 0) * HW + p];
    float c1 = cls[(b * 2 + 1) * HW + p];
    float cmax = fmaxf(c0, c1);

    // prefilter: exact smax <= approx + 2e-6; 0.295 < 0.3 - 2e-6 margin
    float approx = sig_fast(o) * sig_fast(cmax);
    float masked = -1.0f;
    if (approx >= 0.295f) {
        // exact: smax = fmul_rn(sig(o), sig(cmax)) == max(s0, s1) by monotonicity
        float so  = sig_e(o);
        float scm = sig_e(cmax);
        float smax = __fmul_rn(so, scm);
        masked = (smax > SCORE_THRESH) ? smax : -1.0f;
    }

    // label = argmax(s0, s1): c1>c0 suffices except in the rounding-collision
    // band; resolve that band exactly.
    unsigned char lab = 0;
    if (c1 > c0) {
        if (__fsub_rn(c1, c0) < 1e-3f) {
            float so2 = sig_e(o);
            float s0  = __fmul_rn(so2, sig_e(c0));
            float s1  = __fmul_rn(so2, sig_e(c1));
            lab = (s1 > s0) ? 1 : 0;
        } else {
            lab = 1;
        }
    }

    g_scores[t] = masked;
    g_labels[t] = lab;
}

// --------------------------------------------------------------- top-k -----
__device__ __forceinline__ unsigned int ordered_float(float f) {
    unsigned int u = __float_as_uint(f);
    return (u & 0x80000000u) ? ~u : (u | 0x80000000u);
}
// monotone linear bin over (0.3, 1.0]
__device__ __forceinline__ int bin_of(float s) {
    int q = (int)(__fmul_rn(__fsub_rn(s, 0.3f), 1462.857f));
    return (q > NBIN - 1) ? (NBIN - 1) : q;
}

__global__ void topk_kernel()
{
    __shared__ int  hist[NBIN];
    __shared__ int  coarse[NBIN / 4];
    __shared__ int  s_qp, s_cnt, s_fallback, s_valid;
    __shared__ unsigned long long ckey[CAND];
    __shared__ int  cidx[CAND];
    __shared__ unsigned long long s_prefix;
    __shared__ int  s_k;

    int b   = blockIdx.x;
    int tid = threadIdx.x;
    const float* sc = g_scores + b * NA;

    for (int d = tid; d < NBIN; d += 512) hist[d] = 0;
    if (tid == 0) { s_valid = 0; s_cnt = 0; s_fallback = 0; }
    __syncthreads();

    // pass 1: histogram + valid count
    int localv = 0;
    for (int i = tid; i < NA; i += 512) {
        float s = sc[i];
        if (s > SCORE_THRESH) { atomicAdd(&hist[bin_of(s)], 1); localv++; }
    }
    if (localv) atomicAdd(&s_valid, localv);
    __syncthreads();

    if (tid < NBIN / 4)
        coarse[tid] = hist[4 * tid] + hist[4 * tid + 1] + hist[4 * tid + 2] + hist[4 * tid + 3];
    __syncthreads();

    if (tid == 0) {
        if (s_valid < TOPK) {
            s_fallback = 1;
        } else {
            int cum = 0, qp = 0;
            for (int g = NBIN / 4 - 1; g >= 0; --g) {
                if (cum + coarse[g] >= TOPK) {
                    for (int d = 4 * g + 3; d >= 4 * g; --d) {
                        if (cum + hist[d] >= TOPK) { qp = d; break; }
                        cum += hist[d];
                    }
                    break;
                }
                cum += coarse[g];
            }
            s_qp = qp;
        }
    }
    __syncthreads();

    if (!s_fallback) {
        // pass 2: gather candidates (bin >= pivot bin)
        int qp = s_qp;
        for (int i = tid; i < NA; i += 512) {
            float s = sc[i];
            if (s > SCORE_THRESH && bin_of(s) >= qp) {
                int pos = atomicAdd(&s_cnt, 1);
                if (pos < CAND) {
                    ckey[pos] = ((unsigned long long)ordered_float(s) << 32) |
                                (unsigned int)(~(unsigned int)i);
                    cidx[pos] = i;
                } else {
                    s_fallback = 1;
                }
            }
        }
        __syncthreads();
    }

    if (s_fallback) {
        // exact 64-bit 8-pass radix select (rare path; preserves generality)
        if (tid == 0) { s_prefix = 0ull; s_k = TOPK; s_cnt = 0; }
        __syncthreads();
        for (int pp = 7; pp >= 0; --pp) {
            for (int d = tid; d < 256; d += 512) hist[d] = 0;
            __syncthreads();
            unsigned long long pref = s_prefix;
            int sh = (pp + 1) * 8;
            for (int i = tid; i < NA; i += 512) {
                unsigned long long key =
                    ((unsigned long long)ordered_float(sc[i]) << 32) |
                    (unsigned int)(~(unsigned int)i);
                bool match = (pp == 7) || ((key >> sh) == (pref >> sh));
                if (match) atomicAdd(&hist[(unsigned int)(key >> (pp * 8)) & 0xFFu], 1);
            }
            __syncthreads();
            if (tid == 0) {
                int k = s_k;
                for (int d = 255; d >= 0; --d) {
                    int c = hist[d];
                    if (k <= c) { s_prefix = pref | ((unsigned long long)d << (pp * 8)); break; }
                    k -= c;
                }
                s_k = k;
            }
            __syncthreads();
        }
        unsigned long long pivot = s_prefix;
        for (int i = tid; i < NA; i += 512) {
            unsigned long long key =
                ((unsigned long long)ordered_float(sc[i]) << 32) |
                (unsigned int)(~(unsigned int)i);
            if (key >= pivot) {
                int pos = atomicAdd(&s_cnt, 1);
                if (pos < CAND) { ckey[pos] = key; cidx[pos] = i; }
            }
        }
        __syncthreads();
    }

    // pad to CAND
    int cnt = s_cnt; if (cnt > CAND) cnt = CAND;
    for (int s = tid; s < CAND; s += 512) {
        if (s >= cnt) { ckey[s] = 0ull; cidx[s] = 0x7FFFFFFF; }
    }
    __syncthreads();

    // bitonic sort, descending, 1024 elems / 512 threads
    for (int k = 2; k <= CAND; k <<= 1) {
        for (int j = k >> 1; j > 0; j >>= 1) {
            #pragma unroll
            for (int q = 0; q < 2; ++q) {
                int i = tid + q * 512;
                int ixj = i ^ j;
                if (ixj > i) {
                    bool desc = ((i & k) == 0);
                    unsigned long long ka = ckey[i], kb = ckey[ixj];
                    if (desc ? (ka < kb) : (ka > kb)) {
                        ckey[i] = kb; ckey[ixj] = ka;
                        int t2 = cidx[i]; cidx[i] = cidx[ixj]; cidx[ixj] = t2;
                    }
                }
            }
            __syncthreads();
        }
    }

    if (tid < TOPK) g_topidx[b * TOPK + tid] = cidx[tid];
}

// ------------------------------------------- NMS (+ box decode for top-k) --
__global__ void nms_kernel(const float* __restrict__ reg3,
                           const float* __restrict__ reg4,
                           const float* __restrict__ reg5,
                           float* __restrict__ out)
{
    __shared__ float sx1[TOPK], sy1[TOPK], sx2[TOPK], sy2[TOPK];
    __shared__ float sar[TOPK];
    __shared__ unsigned char svalid[TOPK];
    __shared__ unsigned char skeep[TOPK];
    __shared__ unsigned int adj[TOPK][16];

    int b = blockIdx.x;
    int r = threadIdx.x;

    float4 bb = make_float4(0.f, 0.f, 0.f, 0.f);
    float  sc = -1.0f;
    int    lab = 0;

    if (r < TOPK) {
        int idx = g_topidx[b * TOPK + r];
        sc  = g_scores[b * NA + idx];
        lab = (int)g_labels[b * NA + idx];

        // decode box for this selected anchor (same rounding sequence as R4)
        const float* reg; int HW, W, p; float stride;
        if (idx < P3_END)      { reg = reg3; HW = 25600; W = 160; stride = 8.f;  p = idx; }
        else if (idx < P4_END) { reg = reg4; HW = 6400;  W = 80;  stride = 16.f; p = idx - P3_END; }
        else                   { reg = reg5; HW = 1600;  W = 40;  stride = 32.f; p = idx - P4_END; }
        int y = p / W;
        int x = p - y * W;
        float dx = reg[(b * 4 + 0) * HW + p];
        float dy = reg[(b * 4 + 1) * HW + p];
        float dw = reg[(b * 4 + 2) * HW + p];
        float dh = reg[(b * 4 + 3) * HW + p];
        float cx = __fmul_rn(__fadd_rn((float)x, sig_e(dx)), stride);
        float cy = __fmul_rn(__fadd_rn((float)y, sig_e(dy)), stride);
        float w  = __fmul_rn(exp_cr(dw), stride);
        float h  = __fmul_rn(exp_cr(dh), stride);
        float wh = __fdiv_rn(w, 2.0f);
        float hh = __fdiv_rn(h, 2.0f);
        bb.x = __fsub_rn(cx, wh);
        bb.y = __fsub_rn(cy, hh);
        bb.z = __fadd_rn(cx, wh);
        bb.w = __fadd_rn(cy, hh);

        float off = __fmul_rn((float)lab, CLASS_OFFSET);
        float x1 = __fadd_rn(bb.x, off);
        float y1 = __fadd_rn(bb.y, off);
        float x2 = __fadd_rn(bb.z, off);
        float y2 = __fadd_rn(bb.w, off);
        sx1[r] = x1; sy1[r] = y1; sx2[r] = x2; sy2[r] = y2;
        sar[r] = __fmul_rn(__fsub_rn(x2, x1), __fsub_rn(y2, y1));
        svalid[r] = (sc > SCORE_THRESH) ? 1 : 0;
    }
    __syncthreads();

    // adjacency rows
    if (r < TOPK) {
        float x1 = sx1[r], y1 = sy1[r], x2 = sx2[r], y2 = sy2[r], ar = sar[r];
        #pragma unroll 1
        for (int w = 0; w < 16; ++w) {
            unsigned int bits = 0;
            #pragma unroll 1
            for (int jj = 0; jj < 32; ++jj) {
                int j = (w << 5) + jj;
                if (j < TOPK) {
                    float ix1 = fmaxf(x1, sx1[j]);
                    float iy1 = fmaxf(y1, sy1[j]);
                    float ix2 = fminf(x2, sx2[j]);
                    float iy2 = fminf(y2, sy2[j]);
                    float iw = fmaxf(__fsub_rn(ix2, ix1), 0.f);
                    float ih = fmaxf(__fsub_rn(iy2, iy1), 0.f);
                    float inter = __fmul_rn(iw, ih);
                    float uni = __fsub_rn(__fadd_rn(ar, sar[j]), inter);
                    float iou = __fdiv_rn(inter, __fadd_rn(uni, 1e-7f));
                    if (iou >= NMS_THRESH) bits |= (1u << jj);
                }
            }
            adj[r][w] = bits;
        }
    }
    __syncthreads();

    // serial greedy pass on warp 0
    if (threadIdx.x < 32) {
        unsigned int supp = 0;
        int lane = threadIdx.x;
        for (int i = 0; i < TOPK; ++i) {
            unsigned int sw = __shfl_sync(0xFFFFFFFFu, supp, i >> 5);
            bool keep_i = svalid[i] && !((sw >> (i & 31)) & 1u);
            if (lane == 0) skeep[i] = keep_i ? 1 : 0;
            if (keep_i && lane < 16) supp |= adj[i][lane];
        }
    }
    __syncthreads();

    // outputs: [boxes (B*500*4)] [scores] [labels] [keep]
    if (r < TOPK) {
        bool kp = skeep[r] != 0;
        int row = b * TOPK + r;
        float* ob = out + row * 4;
        ob[0] = kp ? bb.x : 0.f;
        ob[1] = kp ? bb.y : 0.f;
        ob[2] = kp ? bb.z : 0.f;
        ob[3] = kp ? bb.w : 0.f;
        const int SBASE = B * TOPK * 4;
        const int LBASE = SBASE + B * TOPK;
        const int KBASE = LBASE + B * TOPK;
        out[SBASE + row] = kp ? sc : 0.f;
        out[LBASE + row] = (float)lab;
        out[KBASE + row] = kp ? 1.f : 0.f;
    }
}

// --------------------------------------------------------------- launch ----
extern "C" void kernel_launch(void* const* d_in, const int* in_sizes, int n_in,
                              void* d_out, int out_size)
{
    const float* cls_p3 = (const float*)d_in[0];
    const float* reg_p3 = (const float*)d_in[1];
    const float* obj_p3 = (const float*)d_in[2];
    const float* cls_p4 = (const float*)d_in[3];
    const float* reg_p4 = (const float*)d_in[4];
    const float* obj_p4 = (const float*)d_in[5];
    const float* cls_p5 = (const float*)d_in[6];
    const float* reg_p5 = (const float*)d_in[7];
    const float* obj_p5 = (const float*)d_in[8];
    float* out = (float*)d_out;

    const int T = 256;
    decode_score_kernel<<<(B * NA + T - 1) / T, T>>>(cls_p3, obj_p3, cls_p4, obj_p4, cls_p5, obj_p5);
    topk_kernel<<<B, 512>>>();
    nms_kernel<<<B, 512>>>(reg_p3, reg_p4, reg_p5, out);
}

// round 6
// speedup vs baseline: 2.5400x; 1.8515x over previous
#include <cuda_runtime.h>
#include <cuda_bf16.h>
#include <math.h>

// Problem constants
#define B 64
#define NA 33600            // 160*160 + 80*80 + 40*40
#define TOPK 500
#define CAND 1024           // candidate sort size
#define NBIN 1024           // linear histogram bins over (0.3, 1.0]
#define SCORE_THRESH 0.3f
#define NMS_THRESH 0.5f
#define CLASS_OFFSET 10000.0f

#define P3_END 25600
#define P4_END 32000

// ---------------- scratch (static device allocations; no runtime alloc) ----
__device__ float              g_scores[B * NA];      // masked scores (fallback path input)
__device__ unsigned long long g_cand[B * NA];        // per-batch candidate keys
__device__ int                g_cnt[B];              // per-batch candidate counts
__device__ int                g_hist[B][NBIN];       // per-batch score histograms
__device__ int                g_topidx[B * TOPK];    // sorted top-k anchor indices
__device__ float              g_topscore[B * TOPK];  // sorted top-k scores

// ------------------------------------------------------------ exp/sigmoid --
// Correctly-rounded float exp via double exp (matches XLA:CPU expf).
// Verified bit-compatible in R4/R5 — DO NOT change.
__device__ __forceinline__ float exp_cr(float x) {
    return (float)exp((double)x);
}
__device__ __forceinline__ float sig_e(float x) {
    float e = exp_cr(-x);
    return __fdiv_rn(1.0f, __fadd_rn(1.0f, e));
}
// fast sigmoid for prefilter only (abs err ~1e-6; 0.295 margin covers it)
__device__ __forceinline__ float sig_fast(float x) {
    return __fdividef(1.0f, 1.0f + __expf(-x));
}

__device__ __forceinline__ unsigned int ordered_float(float f) {
    unsigned int u = __float_as_uint(f);
    return (u & 0x80000000u) ? ~u : (u | 0x80000000u);
}
__device__ __forceinline__ float inv_ordered(unsigned int u) {
    return __uint_as_float((u & 0x80000000u) ? (u ^ 0x80000000u) : ~u);
}
// monotone linear bin over (0.3, 1.0]
__device__ __forceinline__ int bin_of(float s) {
    int q = (int)(__fmul_rn(__fsub_rn(s, 0.3f), 1462.857f));
    return (q > NBIN - 1) ? (NBIN - 1) : q;
}

// ------------------------------------------------------- decode (scores) ---
// Block layout: 256 threads = 256 consecutive anchors of one (batch, level).
// blocks [0,6400): P3 (64b x 100 chunks); [6400,8000): P4 (64 x 25);
// [8000,8448): P5 (64 x 7, last chunk partial).
__global__ void decode_score_kernel(const float* __restrict__ cls3,
                                    const float* __restrict__ obj3,
                                    const float* __restrict__ cls4,
                                    const float* __restrict__ obj4,
                                    const float* __restrict__ cls5,
                                    const float* __restrict__ obj5)
{
    __shared__ float s_o[256], s_c[256];
    __shared__ int   s_t[256];
    __shared__ int   s_n;

    int blk = blockIdx.x;
    const float* cls; const float* obj;
    int b, HW, base, p0;
    if (blk < 6400)      { b = blk / 100;             int c = blk - b * 100;  HW = 25600; base = 0;      p0 = c * 256; cls = cls3; obj = obj3; }
    else if (blk < 8000) { int x = blk - 6400; b = x / 25; int c = x - b * 25; HW = 6400;  base = P3_END; p0 = c * 256; cls = cls4; obj = obj4; }
    else                 { int x = blk - 8000; b = x / 7;  int c = x - b * 7;  HW = 1600;  base = P4_END; p0 = c * 256; cls = cls5; obj = obj5; }

    int tid = threadIdx.x;
    int p = p0 + tid;
    bool inb = p < HW;

    float o = 0.f, c0 = 0.f, c1 = 0.f;
    if (inb) {
        o  = obj[b * HW + p];
        c0 = cls[(b * 2 + 0) * HW + p];
        c1 = cls[(b * 2 + 1) * HW + p];
    }
    float cmax = fmaxf(c0, c1);
    int t = b * NA + base + p;               // global score index
    if (inb) g_scores[t] = -1.0f;            // default (overwritten below if >thresh)

    bool pass = inb && (sig_fast(o) * sig_fast(cmax) >= 0.295f);

    if (tid == 0) s_n = 0;
    __syncthreads();

    // warp-aggregated compaction of prefilter survivors
    unsigned m = __ballot_sync(0xFFFFFFFFu, pass);
    int wcnt = __popc(m);
    int wbase = 0;
    if ((tid & 31) == 0 && wcnt) wbase = atomicAdd(&s_n, wcnt);
    wbase = __shfl_sync(0xFFFFFFFFu, wbase, 0);
    if (pass) {
        int pos = wbase + __popc(m & ((1u << (tid & 31)) - 1u));
        s_o[pos] = o; s_c[pos] = cmax; s_t[pos] = t;
    }
    __syncthreads();

    // dense exact-exp pass over survivors only
    int n = s_n;
    if (tid < n) {
        float so   = sig_e(s_o[tid]);
        float scm  = sig_e(s_c[tid]);
        float smax = __fmul_rn(so, scm);     // == max(s0,s1) by monotonicity
        if (smax > SCORE_THRESH) {
            int tt = s_t[tid];
            g_scores[tt] = smax;
            int ai  = tt - b * NA;
            int pos = atomicAdd(&g_cnt[b], 1);
            g_cand[b * NA + pos] =
                ((unsigned long long)ordered_float(smax) << 32) |
                (unsigned int)(~(unsigned int)ai);
            atomicAdd(&g_hist[b][bin_of(smax)], 1);
        }
    }
}

// --------------------------------------------------------------- top-k -----
__global__ void topk_kernel()
{
    __shared__ int  hist[NBIN];
    __shared__ int  coarse[NBIN / 4];
    __shared__ int  s_qp, s_cnt, s_fallback;
    __shared__ unsigned long long ckey[CAND];
    __shared__ unsigned long long s_prefix;
    __shared__ int  s_k;

    int b   = blockIdx.x;
    int tid = threadIdx.x;
    int cnt_all = g_cnt[b];

    for (int d = tid; d < NBIN; d += 512) hist[d] = g_hist[b][d];
    if (tid == 0) { s_cnt = 0; s_fallback = (cnt_all < TOPK) ? 1 : 0; }
    __syncthreads();

    if (!s_fallback) {
        if (tid < NBIN / 4)
            coarse[tid] = hist[4 * tid] + hist[4 * tid + 1] + hist[4 * tid + 2] + hist[4 * tid + 3];
        __syncthreads();
        if (tid == 0) {
            int cum = 0, qp = 0;
            for (int g = NBIN / 4 - 1; g >= 0; --g) {
                if (cum + coarse[g] >= TOPK) {
                    for (int d = 4 * g + 3; d >= 4 * g; --d) {
                        if (cum + hist[d] >= TOPK) { qp = d; break; }
                        cum += hist[d];
                    }
                    break;
                }
                cum += coarse[g];
            }
            s_qp = qp;
        }
        __syncthreads();

        // gather candidates with bin >= pivot bin from the compact list
        int qp = s_qp;
        const unsigned long long* cl = g_cand + b * NA;
        for (int i = tid; i < cnt_all; i += 512) {
            unsigned long long key = cl[i];
            float s = inv_ordered((unsigned int)(key >> 32));
            if (bin_of(s) >= qp) {
                int pos = atomicAdd(&s_cnt, 1);
                if (pos < CAND) ckey[pos] = key;
                else            s_fallback = 1;
            }
        }
        __syncthreads();
    }

    if (s_fallback) {
        // exact 64-bit 8-pass radix select over full masked score array
        const float* sc = g_scores + b * NA;
        if (tid == 0) { s_prefix = 0ull; s_k = TOPK; s_cnt = 0; }
        __syncthreads();
        for (int pp = 7; pp >= 0; --pp) {
            for (int d = tid; d < 256; d += 512) hist[d] = 0;
            __syncthreads();
            unsigned long long pref = s_prefix;
            int sh = (pp + 1) * 8;
            for (int i = tid; i < NA; i += 512) {
                unsigned long long key =
                    ((unsigned long long)ordered_float(sc[i]) << 32) |
                    (unsigned int)(~(unsigned int)i);
                bool match = (pp == 7) || ((key >> sh) == (pref >> sh));
                if (match) atomicAdd(&hist[(unsigned int)(key >> (pp * 8)) & 0xFFu], 1);
            }
            __syncthreads();
            if (tid == 0) {
                int k = s_k;
                for (int d = 255; d >= 0; --d) {
                    int c = hist[d];
                    if (k <= c) { s_prefix = pref | ((unsigned long long)d << (pp * 8)); break; }
                    k -= c;
                }
                s_k = k;
            }
            __syncthreads();
        }
        unsigned long long pivot = s_prefix;
        for (int i = tid; i < NA; i += 512) {
            unsigned long long key =
                ((unsigned long long)ordered_float(sc[i]) << 32) |
                (unsigned int)(~(unsigned int)i);
            if (key >= pivot) {
                int pos = atomicAdd(&s_cnt, 1);
                if (pos < CAND) ckey[pos] = key;
            }
        }
        __syncthreads();
    }

    // pad + bitonic sort (descending), 1024 elems / 512 threads
    int cnt = s_cnt; if (cnt > CAND) cnt = CAND;
    for (int s = tid; s < CAND; s += 512)
        if (s >= cnt) ckey[s] = 0ull;
    __syncthreads();

    for (int k = 2; k <= CAND; k <<= 1) {
        for (int j = k >> 1; j > 0; j >>= 1) {
            #pragma unroll
            for (int q = 0; q < 2; ++q) {
                int i = tid + q * 512;
                int ixj = i ^ j;
                if (ixj > i) {
                    bool desc = ((i & k) == 0);
                    unsigned long long ka = ckey[i], kb = ckey[ixj];
                    if (desc ? (ka < kb) : (ka > kb)) { ckey[i] = kb; ckey[ixj] = ka; }
                }
            }
            __syncthreads();
        }
    }

    if (tid < TOPK) {
        unsigned long long key = ckey[tid];
        g_topidx  [b * TOPK + tid] = (int)(~(unsigned int)key);
        g_topscore[b * TOPK + tid] = inv_ordered((unsigned int)(key >> 32));
    }
}

// ------------------------------------------- NMS (+ box/label decode) ------
__global__ void nms_kernel(const float* __restrict__ reg3,
                           const float* __restrict__ reg4,
                           const float* __restrict__ reg5,
                           const float* __restrict__ cls3,
                           const float* __restrict__ cls4,
                           const float* __restrict__ cls5,
                           const float* __restrict__ obj3,
                           const float* __restrict__ obj4,
                           const float* __restrict__ obj5,
                           float* __restrict__ out)
{
    __shared__ float4 sbox[512];            // class-offset boxes
    __shared__ float  sar[512];
    __shared__ unsigned int adj[512][16];   // IoU>=0.5 adjacency bitmatrix
    __shared__ unsigned int s_validw[16];
    __shared__ unsigned char skeep[512];

    int b = blockIdx.x;
    int r = threadIdx.x;

    float4 bb = make_float4(0.f, 0.f, 0.f, 0.f);
    float  sc = -1.0f;
    int    lab = 0;
    bool   validf = false;

    if (r < TOPK) {
        int idx = g_topidx[b * TOPK + r];
        sc = g_topscore[b * TOPK + r];

        const float* reg; const float* cls; const float* obj;
        int HW, W, p; float stride;
        if (idx < P3_END)      { reg = reg3; cls = cls3; obj = obj3; HW = 25600; W = 160; stride = 8.f;  p = idx; }
        else if (idx < P4_END) { reg = reg4; cls = cls4; obj = obj4; HW = 6400;  W = 80;  stride = 16.f; p = idx - P3_END; }
        else                   { reg = reg5; cls = cls5; obj = obj5; HW = 1600;  W = 40;  stride = 32.f; p = idx - P4_END; }
        int y = p / W;
        int x = p - y * W;

        // box decode (same rounding sequence as R4/R5)
        float dx = reg[(b * 4 + 0) * HW + p];
        float dy = reg[(b * 4 + 1) * HW + p];
        float dw = reg[(b * 4 + 2) * HW + p];
        float dh = reg[(b * 4 + 3) * HW + p];
        float cx = __fmul_rn(__fadd_rn((float)x, sig_e(dx)), stride);
        float cy = __fmul_rn(__fadd_rn((float)y, sig_e(dy)), stride);
        float w  = __fmul_rn(exp_cr(dw), stride);
        float h  = __fmul_rn(exp_cr(dh), stride);
        float wh = __fdiv_rn(w, 2.0f);
        float hh = __fdiv_rn(h, 2.0f);
        bb.x = __fsub_rn(cx, wh);
        bb.y = __fsub_rn(cy, hh);
        bb.z = __fadd_rn(cx, wh);
        bb.w = __fadd_rn(cy, hh);

        // label (exact band check, same as before)
        float c0 = cls[(b * 2 + 0) * HW + p];
        float c1 = cls[(b * 2 + 1) * HW + p];
        if (c1 > c0) {
            if (__fsub_rn(c1, c0) < 1e-3f) {
                float o   = obj[b * HW + p];
                float so2 = sig_e(o);
                float s0  = __fmul_rn(so2, sig_e(c0));
                float s1  = __fmul_rn(so2, sig_e(c1));
                lab = (s1 > s0) ? 1 : 0;
            } else {
                lab = 1;
            }
        }

        float off = __fmul_rn((float)lab, CLASS_OFFSET);
        float x1 = __fadd_rn(bb.x, off);
        float y1 = __fadd_rn(bb.y, off);
        float x2 = __fadd_rn(bb.z, off);
        float y2 = __fadd_rn(bb.w, off);
        sbox[r] = make_float4(x1, y1, x2, y2);
        sar[r]  = __fmul_rn(__fsub_rn(x2, x1), __fsub_rn(y2, y1));
        validf  = (sc > SCORE_THRESH);
    } else {
        sbox[r] = make_float4(0.f, 0.f, 0.f, 0.f);
        sar[r]  = 0.f;
    }

    // pack valid bits: one 32-bit word per warp
    unsigned vb = __ballot_sync(0xFFFFFFFFu, validf);
    if ((r & 31) == 0) s_validw[r >> 5] = vb;

    #pragma unroll
    for (int w = 0; w < 16; ++w) adj[r][w] = 0u;
    __syncthreads();

    // balanced pair enumeration: thread r handles cyclic distances 1..255
    // (+256 for r<256); each unordered pair computed exactly once.
    {
        float4 mb = sbox[r];
        float  ar = sar[r];
        int kmax = (r < 256) ? 256 : 255;
        for (int k = 1; k <= kmax; ++k) {
            int j = (r + k) & 511;
            float4 bj = sbox[j];
            float  aj = sar[j];
            float ix1 = fmaxf(mb.x, bj.x);
            float iy1 = fmaxf(mb.y, bj.y);
            float ix2 = fminf(mb.z, bj.z);
            float iy2 = fminf(mb.w, bj.w);
            float iw  = fmaxf(__fsub_rn(ix2, ix1), 0.f);
            float ih  = fmaxf(__fsub_rn(iy2, iy1), 0.f);
            float inter = __fmul_rn(iw, ih);
            float uniP  = __fadd_rn(__fsub_rn(__fadd_rn(ar, aj), inter), 1e-7f);
            // decision: rn(inter/uniP) >= 0.5  via compare, exact div in guard band
            float t    = __fmul_rn(0.5f, uniP);
            float diff = __fsub_rn(inter, t);
            bool hit;
            if (fabsf(diff) <= __fmul_rn(1e-6f, t)) {
                float iou = __fdiv_rn(inter, uniP);
                hit = (iou >= NMS_THRESH);
            } else {
                hit = (diff > 0.f);
            }
            if (hit) {
                atomicOr(&adj[r][j >> 5], 1u << (j & 31));
                atomicOr(&adj[j][r >> 5], 1u << (r & 31));
            }
        }
    }
    __syncthreads();

    // serial greedy on warp 0: avail = valid & ~suppressed, per-lane word
    if (r < 32) {
        int lane = r;
        unsigned avail   = (lane < 16) ? s_validw[lane] : 0u;
        unsigned nextadj = (lane < 16) ? adj[0][lane]   : 0u;
        for (int i = 0; i < TOPK; ++i) {
            unsigned myadj = nextadj;
            nextadj = (lane < 16 && i + 1 < 512) ? adj[i + 1][lane] : 0u;
            unsigned aw = __shfl_sync(0xFFFFFFFFu, avail, i >> 5);
            bool keep_i = (aw >> (i & 31)) & 1u;
            if (lane == 0) skeep[i] = keep_i ? 1 : 0;
            if (keep_i) avail &= ~myadj;
        }
    }
    __syncthreads();

    // outputs: [boxes (B*500*4)] [scores] [labels] [keep]
    if (r < TOPK) {
        bool kp = skeep[r] != 0;
        int row = b * TOPK + r;
        float* ob = out + row * 4;
        ob[0] = kp ? bb.x : 0.f;
        ob[1] = kp ? bb.y : 0.f;
        ob[2] = kp ? bb.z : 0.f;
        ob[3] = kp ? bb.w : 0.f;
        const int SBASE = B * TOPK * 4;
        const int LBASE = SBASE + B * TOPK;
        const int KBASE = LBASE + B * TOPK;
        out[SBASE + row] = kp ? sc : 0.f;
        out[LBASE + row] = (float)lab;
        out[KBASE + row] = kp ? 1.f : 0.f;
    }
}

// --------------------------------------------------------------- launch ----
extern "C" void kernel_launch(void* const* d_in, const int* in_sizes, int n_in,
                              void* d_out, int out_size)
{
    const float* cls_p3 = (const float*)d_in[0];
    const float* reg_p3 = (const float*)d_in[1];
    const float* obj_p3 = (const float*)d_in[2];
    const float* cls_p4 = (const float*)d_in[3];
    const float* reg_p4 = (const float*)d_in[4];
    const float* obj_p4 = (const float*)d_in[5];
    const float* cls_p5 = (const float*)d_in[6];
    const float* reg_p5 = (const float*)d_in[7];
    const float* obj_p5 = (const float*)d_in[8];
    float* out = (float*)d_out;

    // zero per-batch counters + histograms (graph-capturable async memsets)
    void* p_cnt = nullptr;  void* p_hist = nullptr;
    cudaGetSymbolAddress(&p_cnt,  g_cnt);
    cudaGetSymbolAddress(&p_hist, g_hist);
    cudaMemsetAsync(p_cnt,  0, B * sizeof(int), 0);
    cudaMemsetAsync(p_hist, 0, B * NBIN * sizeof(int), 0);

    decode_score_kernel<<<8448, 256>>>(cls_p3, obj_p3, cls_p4, obj_p4, cls_p5, obj_p5);
    topk_kernel<<<B, 512>>>();
    nms_kernel<<<B, 512>>>(reg_p3, reg_p4, reg_p5,
                           cls_p3, cls_p4, cls_p5,
                           obj_p3, obj_p4, obj_p5, out);
}